// round 15
// baseline (speedup 1.0000x reference)
#include <cuda_runtime.h>
#include <cuda_bf16.h>
#include <math.h>
#include <stdint.h>

// Problem constants
#define B_SZ 4
#define SEQ  2048
#define DM   1024
#define NH   16
#define DH   64
#define NTOK (B_SZ * SEQ)   // 8192

// ---------------------------------------------------------------------------
// Scratch (device globals).
// g_Q/g_K: tf32 bits, [B,H,S, p8(dh)]  (Q pre-scaled by 0.125*log2e)
// g_V:     tf32 bits, [B,H, S/64, dh, p8(s%64)]
// g_ctx:   tf32 bits  [B*S, DM]
// g_xt:    tf32 bits of x;  g_Wt: tf32 bits of Wq,Wk,Wv,Wo
// ---------------------------------------------------------------------------
__device__ uint32_t g_Q[(size_t)B_SZ * NH * SEQ * DH];
__device__ uint32_t g_K[(size_t)B_SZ * NH * SEQ * DH];
__device__ uint32_t g_V[(size_t)B_SZ * NH * SEQ * DH];
__device__ uint32_t g_ctx[(size_t)NTOK * DM];
__device__ uint32_t g_xt[(size_t)NTOK * DM];
__device__ uint32_t g_Wt[(size_t)4 * DM * DM];

#define QSCALE 0.180336880f   // 0.125 * log2(e): softmax in log2 domain

__device__ __forceinline__ int p8(int k) {
    return (k & ~7) + ((k & 3) << 1) + ((k >> 2) & 1);
}
__device__ __forceinline__ uint32_t rn_tf32(float x) {
    uint32_t r;
    asm("cvt.rna.tf32.f32 %0, %1;" : "=r"(r) : "f"(x));
    return r;
}
__device__ __forceinline__ float ex2(float x) {
    float y;
    asm("ex2.approx.f32 %0, %1;" : "=f"(y) : "f"(x));
    return y;
}
__device__ __forceinline__ uint32_t smem_u32(const void* p) {
    uint32_t a;
    asm("{ .reg .u64 t; cvta.to.shared.u64 t, %1; cvt.u32.u64 %0, t; }"
        : "=r"(a) : "l"(p));
    return a;
}
__device__ __forceinline__ void mma_tf32(float* c, const uint32_t* a,
                                         uint32_t b0, uint32_t b1) {
    asm volatile(
        "mma.sync.aligned.m16n8k8.row.col.f32.tf32.tf32.f32 "
        "{%0,%1,%2,%3}, {%4,%5,%6,%7}, {%8,%9}, {%0,%1,%2,%3};"
        : "+f"(c[0]), "+f"(c[1]), "+f"(c[2]), "+f"(c[3])
        : "r"(a[0]), "r"(a[1]), "r"(a[2]), "r"(a[3]), "r"(b0), "r"(b1));
}

#define CP16(dst32, src) \
    asm volatile("cp.async.cg.shared.global [%0], [%1], 16;" \
                 :: "r"(dst32), "l"(src) : "memory")
#define CP_COMMIT() asm volatile("cp.async.commit_group;" ::: "memory")
#define CP_WAIT0()  asm volatile("cp.async.wait_group 0;" ::: "memory")
#define CP_WAIT1()  asm volatile("cp.async.wait_group 1;" ::: "memory")

// ---------------------------------------------------------------------------
// Prep (single launch): x and the 4 weights -> tf32 bits (rna).
// ---------------------------------------------------------------------------
#define NX  ((size_t)NTOK * DM)      // 8388608
#define NW  ((size_t)DM * DM)        // 1048576

__global__ __launch_bounds__(256) void prep_all(
    const float* __restrict__ x,
    const float* __restrict__ Wq, const float* __restrict__ Wk,
    const float* __restrict__ Wv, const float* __restrict__ Wo,
    uint32_t* __restrict__ xt, uint32_t* __restrict__ Wt)
{
    size_t i = ((size_t)blockIdx.x * 256 + threadIdx.x) * 4;
    const float* src;
    uint32_t* dst;
    size_t off;
    if (i < NX) {
        src = x; dst = xt; off = i;
    } else {
        size_t j = i - NX;
        int w = (int)(j / NW);
        off = j % NW;
        src = (w == 0) ? Wq : (w == 1) ? Wk : (w == 2) ? Wv : Wo;
        dst = Wt + (size_t)w * NW;
    }
    float4 v = *(const float4*)&src[off];
    *(uint4*)&dst[off] = make_uint4(rn_tf32(v.x), rn_tf32(v.y),
                                    rn_tf32(v.z), rn_tf32(v.w));
}

// ---------------------------------------------------------------------------
// TF32 mma GEMM: BM=128, BN=128, BK=32; 256 thr = 2(M) x 4(N) warps;
// per-warp 64x32. THREE-stage cp.async pipeline with wait_group 1 so each
// 48KB chunk copy has two compute-chunks of latency cover (R14 ncu: nothing
// saturated -> latency-bound at wait_group 0).
// mode 0: fp32 out [M,DM] | 1: Q (xQSCALE, p8) | 2: K (p8) | 3: V transposed
// ---------------------------------------------------------------------------
#define AS_U 4608            // 128*36
#define BS_U 4352            // 32*136
#define ST_U (AS_U + BS_U)   // 8960 per stage
#define GEMM_SMEM (3 * ST_U * 4)     // 107520 B; x2 CTAs = 215KB < 228KB

__device__ __forceinline__ void gemm_body(
    const uint32_t* __restrict__ A, const uint32_t* __restrict__ W,
    const float* __restrict__ bias, void* __restrict__ outv, int mode)
{
    extern __shared__ uint32_t gsm[];
    const int tid  = threadIdx.x;
    const int warp = tid >> 5, lane = tid & 31;
    const int wm = warp >> 2, wn = warp & 3;
    const int g  = lane >> 2, tig = lane & 3;
    const int m0 = blockIdx.y * 128;
    const int n0 = blockIdx.x * 128;
    const uint32_t sb = smem_u32(gsm);

    float acc[4][4][4];
#pragma unroll
    for (int mt = 0; mt < 4; ++mt)
#pragma unroll
        for (int nt = 0; nt < 4; ++nt)
#pragma unroll
            for (int r = 0; r < 4; ++r) acc[mt][nt][r] = 0.f;

    auto issue_chunk = [&](int c) {
        const int k0 = c * 32;
        const int st = c % 3;
        const uint32_t ab = sb + (st * ST_U) * 4;
        const uint32_t bb = ab + AS_U * 4;
#pragma unroll
        for (int i = 0; i < 4; ++i) {
            int it = i * 256 + tid;
            int r = it >> 3, c4 = it & 7;
            CP16(ab + (r * 36 + c4 * 4) * 4,
                 &A[(size_t)(m0 + r) * DM + k0 + c4 * 4]);
        }
#pragma unroll
        for (int i = 0; i < 4; ++i) {
            int it = i * 256 + tid;
            int k = it >> 5, n4 = it & 31;
            CP16(bb + (k * 136 + n4 * 4) * 4,
                 &W[(size_t)(k0 + k) * DM + n0 + n4 * 4]);
        }
    };

    issue_chunk(0);
    CP_COMMIT();
    issue_chunk(1);
    CP_COMMIT();

    for (int c = 0; c < 32; ++c) {
        CP_WAIT1();        // chunk c landed; chunk c+1 may still be in flight
        __syncthreads();   // also: all warps done with stage (c-1)%3
        if (c + 2 < 32) { issue_chunk(c + 2); CP_COMMIT(); }

        const uint32_t* As = gsm + (c % 3) * ST_U;
        const uint32_t* Bs = As + AS_U;
#pragma unroll
        for (int kk = 0; kk < 32; kk += 8) {
            uint32_t a[4][4], b[4][2];
#pragma unroll
            for (int mt = 0; mt < 4; ++mt) {
                int row = wm * 64 + mt * 16;
                a[mt][0] = As[(row + g    ) * 36 + kk + tig];
                a[mt][1] = As[(row + g + 8) * 36 + kk + tig];
                a[mt][2] = As[(row + g    ) * 36 + kk + tig + 4];
                a[mt][3] = As[(row + g + 8) * 36 + kk + tig + 4];
            }
#pragma unroll
            for (int nt = 0; nt < 4; ++nt) {
                int coln = wn * 32 + nt * 8 + g;
                b[nt][0] = Bs[(kk + tig    ) * 136 + coln];
                b[nt][1] = Bs[(kk + tig + 4) * 136 + coln];
            }
#pragma unroll
            for (int mt = 0; mt < 4; ++mt)
#pragma unroll
                for (int nt = 0; nt < 4; ++nt)
                    mma_tf32(acc[mt][nt], a[mt], b[nt][0], b[nt][1]);
        }
    }

#pragma unroll
    for (int mt = 0; mt < 4; ++mt) {
#pragma unroll
        for (int nt = 0; nt < 4; ++nt) {
            int col  = n0 + wn * 32 + nt * 8 + 2 * tig;
            float2 bv = *(const float2*)&bias[col];
#pragma unroll
            for (int hh = 0; hh < 2; ++hh) {
                int t = m0 + wm * 64 + mt * 16 + g + hh * 8;
                float ox = acc[mt][nt][hh * 2 + 0] + bv.x;
                float oy = acc[mt][nt][hh * 2 + 1] + bv.y;
                if (mode == 0) {
                    *(float2*)&((float*)outv)[(size_t)t * DM + col] =
                        make_float2(ox, oy);
                } else {
                    int bidx = t >> 11;
                    int srow = t & (SEQ - 1);
                    int head = col >> 6;
                    int dh   = col & (DH - 1);
                    uint32_t* dst = (uint32_t*)outv;
                    size_t hb = (size_t)(bidx * NH + head) * SEQ * DH;
                    if (mode != 3) {
                        float sc = (mode == 1) ? QSCALE : 1.0f;
                        dst[hb + (size_t)srow * DH + p8(dh)] =
                            rn_tf32(ox * sc);
                        dst[hb + (size_t)srow * DH + p8(dh + 1)] =
                            rn_tf32(oy * sc);
                    } else {
                        size_t base = hb + (size_t)(srow >> 6) * (DH * 64)
                                      + p8(srow & 63);
                        dst[base + (size_t)dh * 64]       = rn_tf32(ox);
                        dst[base + (size_t)(dh + 1) * 64] = rn_tf32(oy);
                    }
                }
            }
        }
    }
}

__global__ __launch_bounds__(256, 2) void qkv_gemm(
    const uint32_t* __restrict__ xt, const uint32_t* __restrict__ Wt,
    const float* __restrict__ bq, const float* __restrict__ bk,
    const float* __restrict__ bv,
    uint32_t* __restrict__ Qo, uint32_t* __restrict__ Ko,
    uint32_t* __restrict__ Vo)
{
    const int z = blockIdx.z;
    const uint32_t* W = Wt + (size_t)z * DM * DM;
    const float* bias = (z == 0) ? bq : (z == 1) ? bk : bv;
    void* out = (z == 0) ? (void*)Qo : (z == 1) ? (void*)Ko : (void*)Vo;
    gemm_body(xt, W, bias, out, z + 1);
}

__global__ __launch_bounds__(256, 2) void o_gemm(
    const uint32_t* __restrict__ ctx, const uint32_t* __restrict__ Wt,
    const float* __restrict__ bo, float* __restrict__ out)
{
    gemm_body(ctx, Wt + (size_t)3 * DM * DM, bo, out, 0);
}

// ---------------------------------------------------------------------------
// TF32 mma flash attention (unchanged from R14-validated version).
// ---------------------------------------------------------------------------
#define KS_STR 72
#define VS_STR 72
#define PS_STR 76
#define PS_U32 (128 * PS_STR)          // 9728
#define KS_U32 (64 * KS_STR)           // 4608
#define KV_U32 (2 * KS_U32)            // 9216 per buffer (K + V)
#define FLASH_SMEM ((PS_U32 + 2 * KV_U32) * 4)   // 112640 B

__global__ __launch_bounds__(128, 2) void flash_mma(
    const uint32_t* __restrict__ Q, const uint32_t* __restrict__ K,
    const uint32_t* __restrict__ V)
{
    extern __shared__ uint32_t sm4[];
    uint32_t* Ps = sm4;
    const uint32_t sb = smem_u32(sm4);

    const int tid  = threadIdx.x;
    const int warp = tid >> 5, lane = tid & 31;
    const int g    = lane >> 2;
    const int tig  = lane & 3;
    const int qt = blockIdx.x;
    const int h  = blockIdx.y;
    const int b  = blockIdx.z;

    const size_t head_off = (size_t)(b * NH + h) * SEQ * DH;
    const uint32_t* Qg = Q + head_off + (size_t)qt * 128 * DH;
    const uint32_t* Kg = K + head_off;
    const uint32_t* Vg = V + head_off;

    auto issue_kv = [&](int kb) {
        const uint32_t kbase = sb + (PS_U32 + (kb & 1) * KV_U32) * 4;
        const uint32_t vbase = kbase + KS_U32 * 4;
#pragma unroll
        for (int i = 0; i < 8; ++i) {
            int it = i * 128 + tid;
            int r = it >> 4, c4 = (it & 15) * 4;
            CP16(kbase + (r * KS_STR + c4) * 4,
                 &Kg[(size_t)(kb * 64 + r) * DH + c4]);
            CP16(vbase + (r * VS_STR + c4) * 4,
                 &Vg[(size_t)kb * (DH * 64) + r * 64 + c4]);
        }
    };

    issue_kv(0);
    CP_COMMIT();

    uint32_t qf[2][8][4];
#pragma unroll
    for (int mt = 0; mt < 2; ++mt) {
        const int row = warp * 32 + mt * 16 + g;
#pragma unroll
        for (int kk = 0; kk < 8; ++kk) {
            uint2 q02 = *(const uint2*)&Qg[(size_t)row * DH + kk * 8 + 2 * tig];
            uint2 q13 = *(const uint2*)&Qg[(size_t)(row + 8) * DH + kk * 8 + 2 * tig];
            qf[mt][kk][0] = q02.x; qf[mt][kk][2] = q02.y;
            qf[mt][kk][1] = q13.x; qf[mt][kk][3] = q13.y;
        }
    }

    float o[2][8][4];
#pragma unroll
    for (int mt = 0; mt < 2; ++mt)
#pragma unroll
        for (int nt = 0; nt < 8; ++nt)
#pragma unroll
            for (int r = 0; r < 4; ++r) o[mt][nt][r] = 0.f;
    float m[2][2], l[2][2];
#pragma unroll
    for (int mt = 0; mt < 2; ++mt) {
        m[mt][0] = m[mt][1] = -1e30f;
        l[mt][0] = l[mt][1] = 0.f;
    }

    for (int kb = 0; kb < SEQ / 64; ++kb) {
        CP_WAIT0();
        __syncthreads();
        if (kb + 1 < SEQ / 64) { issue_kv(kb + 1); CP_COMMIT(); }

        const uint32_t* Ks = sm4 + PS_U32 + (kb & 1) * KV_U32;
        const uint32_t* Vs = Ks + KS_U32;

        float s[2][8][4];
#pragma unroll
        for (int mt = 0; mt < 2; ++mt)
#pragma unroll
            for (int nt = 0; nt < 8; ++nt)
#pragma unroll
                for (int r = 0; r < 4; ++r) s[mt][nt][r] = 0.f;
#pragma unroll
        for (int kk = 0; kk < 8; ++kk) {
#pragma unroll
            for (int nt = 0; nt < 8; ++nt) {
                uint2 bb = *(const uint2*)
                    &Ks[(nt * 8 + g) * KS_STR + kk * 8 + 2 * tig];
                mma_tf32(s[0][nt], qf[0][kk], bb.x, bb.y);
                mma_tf32(s[1][nt], qf[1][kk], bb.x, bb.y);
            }
        }

        // Online softmax in log2 domain (scores pre-scaled by log2e)
#pragma unroll
        for (int mt = 0; mt < 2; ++mt) {
            float mx0 = -1e30f, mx1 = -1e30f;
#pragma unroll
            for (int nt = 0; nt < 8; ++nt) {
                mx0 = fmaxf(mx0, fmaxf(s[mt][nt][0], s[mt][nt][1]));
                mx1 = fmaxf(mx1, fmaxf(s[mt][nt][2], s[mt][nt][3]));
            }
#pragma unroll
            for (int off = 1; off < 4; off <<= 1) {
                mx0 = fmaxf(mx0, __shfl_xor_sync(0xffffffffu, mx0, off, 4));
                mx1 = fmaxf(mx1, __shfl_xor_sync(0xffffffffu, mx1, off, 4));
            }
            float mn0 = fmaxf(m[mt][0], mx0), mn1 = fmaxf(m[mt][1], mx1);
            float c0 = ex2(m[mt][0] - mn0), c1 = ex2(m[mt][1] - mn1);
            m[mt][0] = mn0; m[mt][1] = mn1;

            float sum0 = 0.f, sum1 = 0.f;
            const int row = warp * 32 + mt * 16 + g;
#pragma unroll
            for (int nt = 0; nt < 8; ++nt) {
                s[mt][nt][0] = ex2(s[mt][nt][0] - mn0);
                s[mt][nt][1] = ex2(s[mt][nt][1] - mn0);
                s[mt][nt][2] = ex2(s[mt][nt][2] - mn1);
                s[mt][nt][3] = ex2(s[mt][nt][3] - mn1);
                sum0 += s[mt][nt][0] + s[mt][nt][1];
                sum1 += s[mt][nt][2] + s[mt][nt][3];
                *(uint2*)&Ps[row * PS_STR + nt * 8 + 2 * tig] =
                    make_uint2(rn_tf32(s[mt][nt][0]), rn_tf32(s[mt][nt][1]));
                *(uint2*)&Ps[(row + 8) * PS_STR + nt * 8 + 2 * tig] =
                    make_uint2(rn_tf32(s[mt][nt][2]), rn_tf32(s[mt][nt][3]));
            }
#pragma unroll
            for (int off = 1; off < 4; off <<= 1) {
                sum0 += __shfl_xor_sync(0xffffffffu, sum0, off, 4);
                sum1 += __shfl_xor_sync(0xffffffffu, sum1, off, 4);
            }
            l[mt][0] = l[mt][0] * c0 + sum0;
            l[mt][1] = l[mt][1] * c1 + sum1;
#pragma unroll
            for (int nt = 0; nt < 8; ++nt) {
                o[mt][nt][0] *= c0; o[mt][nt][1] *= c0;
                o[mt][nt][2] *= c1; o[mt][nt][3] *= c1;
            }
        }
        __syncwarp();

#pragma unroll
        for (int kk = 0; kk < 8; ++kk) {
            uint32_t a0[4], a1[4];
            const int r0 = warp * 32 + g;
            a0[0] = Ps[r0 * PS_STR + kk * 8 + tig];
            a0[1] = Ps[(r0 + 8) * PS_STR + kk * 8 + tig];
            a0[2] = Ps[r0 * PS_STR + kk * 8 + tig + 4];
            a0[3] = Ps[(r0 + 8) * PS_STR + kk * 8 + tig + 4];
            a1[0] = Ps[(r0 + 16) * PS_STR + kk * 8 + tig];
            a1[1] = Ps[(r0 + 24) * PS_STR + kk * 8 + tig];
            a1[2] = Ps[(r0 + 16) * PS_STR + kk * 8 + tig + 4];
            a1[3] = Ps[(r0 + 24) * PS_STR + kk * 8 + tig + 4];
#pragma unroll
            for (int nt = 0; nt < 8; ++nt) {
                uint2 bb = *(const uint2*)
                    &Vs[(nt * 8 + g) * VS_STR + kk * 8 + 2 * tig];
                mma_tf32(o[0][nt], a0, bb.x, bb.y);
                mma_tf32(o[1][nt], a1, bb.x, bb.y);
            }
        }
    }

#pragma unroll
    for (int mt = 0; mt < 2; ++mt) {
        const float inv0 = 1.f / l[mt][0], inv1 = 1.f / l[mt][1];
        const int row0 = qt * 128 + warp * 32 + mt * 16 + g;
#pragma unroll
        for (int nt = 0; nt < 8; ++nt) {
            int col = h * DH + nt * 8 + 2 * tig;
            *(uint2*)&g_ctx[(size_t)(b * SEQ + row0) * DM + col] =
                make_uint2(rn_tf32(o[mt][nt][0] * inv0),
                           rn_tf32(o[mt][nt][1] * inv0));
            *(uint2*)&g_ctx[(size_t)(b * SEQ + row0 + 8) * DM + col] =
                make_uint2(rn_tf32(o[mt][nt][2] * inv1),
                           rn_tf32(o[mt][nt][3] * inv1));
        }
    }
}

// ---------------------------------------------------------------------------
// Launch
// ---------------------------------------------------------------------------
extern "C" void kernel_launch(void* const* d_in, const int* in_sizes, int n_in,
                              void* d_out, int out_size)
{
    const float* x  = (const float*)d_in[0];
    const float* Wq = (const float*)d_in[1];
    const float* bq = (const float*)d_in[2];
    const float* Wk = (const float*)d_in[3];
    const float* bk = (const float*)d_in[4];
    const float* Wv = (const float*)d_in[5];
    const float* bv = (const float*)d_in[6];
    const float* Wo = (const float*)d_in[7];
    const float* bo = (const float*)d_in[8];
    float* out = (float*)d_out;

    uint32_t *Qp, *Kp, *Vp, *Cp, *Xp, *Wp;
    cudaGetSymbolAddress((void**)&Qp, g_Q);
    cudaGetSymbolAddress((void**)&Kp, g_K);
    cudaGetSymbolAddress((void**)&Vp, g_V);
    cudaGetSymbolAddress((void**)&Cp, g_ctx);
    cudaGetSymbolAddress((void**)&Xp, g_xt);
    cudaGetSymbolAddress((void**)&Wp, g_Wt);

    cudaFuncSetAttribute(flash_mma,
                         cudaFuncAttributeMaxDynamicSharedMemorySize, FLASH_SMEM);
    cudaFuncSetAttribute(qkv_gemm,
                         cudaFuncAttributeMaxDynamicSharedMemorySize, GEMM_SMEM);
    cudaFuncSetAttribute(o_gemm,
                         cudaFuncAttributeMaxDynamicSharedMemorySize, GEMM_SMEM);

    // Prep: x + 4 weights -> tf32 bits, one launch
    prep_all<<<(int)((NX + 4 * NW) / 1024), 256>>>(x, Wq, Wk, Wv, Wo, Xp, Wp);

    qkv_gemm<<<dim3(DM / 128, NTOK / 128, 3), 256, GEMM_SMEM>>>(
        Xp, Wp, bq, bk, bv, Qp, Kp, Vp);

    flash_mma<<<dim3(SEQ / 128, NH, B_SZ), 128, FLASH_SMEM>>>(Qp, Kp, Vp);

    o_gemm<<<dim3(DM / 128, NTOK / 128), 256, GEMM_SMEM>>>(Cp, Wp, bo, out);
}

// round 16
// speedup vs baseline: 1.1903x; 1.1903x over previous
#include <cuda_runtime.h>
#include <cuda_fp16.h>
#include <math.h>
#include <stdint.h>

// Problem constants
#define B_SZ 4
#define SEQ  2048
#define DM   1024
#define NH   16
#define DH   64
#define NTOK (B_SZ * SEQ)   // 8192
#define K2   (DM / 2)       // 512 u32 per row of x/ctx

// ---------------------------------------------------------------------------
// Scratch (device globals) — all matrix data as packed fp16 pairs (u32).
// g_xh:  [NTOK][512]  natural pairs of x
// g_Wh:  4 x [512][1024] k-pair-interleaved: u32[k2][n] = (W[2k2][n], W[2k2+1][n])
// g_Qh:  [B,H,S,32]   (Q * QSCALE) natural dh pairs
// g_Kh:  [B,H,32,SEQ] dh-pair-interleaved: u32[d2][s] = (K[s][2d2], K[s][2d2+1])
// g_Vh:  [B,H,S/64,32,64] row-pair-interleaved per 64-block:
//        u32[j2][dh] = (V[blk*64+2j2][dh], V[blk*64+2j2+1][dh])
// g_ctxh:[NTOK][512]  natural pairs of ctx
// ---------------------------------------------------------------------------
__device__ uint32_t g_xh[(size_t)NTOK * K2];
__device__ uint32_t g_Wh[(size_t)4 * K2 * DM];
__device__ uint32_t g_Qh[(size_t)B_SZ * NH * SEQ * 32];
__device__ uint32_t g_Kh[(size_t)B_SZ * NH * 32 * SEQ];
__device__ uint32_t g_Vh[(size_t)B_SZ * NH * 32 * SEQ];
__device__ uint32_t g_ctxh[(size_t)NTOK * K2];

#define QSCALE 0.180336880f   // 0.125 * log2(e): softmax in log2 domain

__device__ __forceinline__ uint32_t pk(float a, float b) {
    half2 h = __floats2half2_rn(a, b);
    return *(uint32_t*)&h;
}
__device__ __forceinline__ float ex2(float x) {
    float y;
    asm("ex2.approx.f32 %0, %1;" : "=f"(y) : "f"(x));
    return y;
}
__device__ __forceinline__ uint32_t smem_u32(const void* p) {
    uint32_t a;
    asm("{ .reg .u64 t; cvta.to.shared.u64 t, %1; cvt.u32.u64 %0, t; }"
        : "=r"(a) : "l"(p));
    return a;
}
__device__ __forceinline__ void mma_f16(float* c, const uint32_t* a,
                                        uint32_t b0, uint32_t b1) {
    asm volatile(
        "mma.sync.aligned.m16n8k16.row.col.f32.f16.f16.f32 "
        "{%0,%1,%2,%3}, {%4,%5,%6,%7}, {%8,%9}, {%0,%1,%2,%3};"
        : "+f"(c[0]), "+f"(c[1]), "+f"(c[2]), "+f"(c[3])
        : "r"(a[0]), "r"(a[1]), "r"(a[2]), "r"(a[3]), "r"(b0), "r"(b1));
}

#define CP16(dst32, src) \
    asm volatile("cp.async.cg.shared.global [%0], [%1], 16;" \
                 :: "r"(dst32), "l"(src) : "memory")
#define CP_COMMIT() asm volatile("cp.async.commit_group;" ::: "memory")
#define CP_WAIT0()  asm volatile("cp.async.wait_group 0;" ::: "memory")

// ---------------------------------------------------------------------------
// Prep (single launch): x -> natural fp16 pairs; W -> k-pair-interleaved.
// ---------------------------------------------------------------------------
#define NX   ((size_t)NTOK * DM)     // 8388608 floats
#define NW   ((size_t)DM * DM)       // 1048576 floats
#define XTHR (NX / 4)                // 2097152 threads (4 floats each)
#define WTHR (NW / 8)                // 131072 threads per W (4 u32 each)

__global__ __launch_bounds__(256) void prep_all(
    const float* __restrict__ x,
    const float* __restrict__ Wq, const float* __restrict__ Wk,
    const float* __restrict__ Wv, const float* __restrict__ Wo,
    uint32_t* __restrict__ xh, uint32_t* __restrict__ Wh)
{
    size_t i = (size_t)blockIdx.x * 256 + threadIdx.x;
    if (i < XTHR) {
        float4 v = *(const float4*)&x[i * 4];
        xh[i * 2 + 0] = pk(v.x, v.y);
        xh[i * 2 + 1] = pk(v.z, v.w);
    } else {
        size_t j = i - XTHR;
        int w = (int)(j / WTHR);
        size_t r = j % WTHR;
        int k2 = (int)(r >> 8);          // 0..511
        int n  = (int)(r & 255) * 4;     // 0..1020
        const float* W = (w == 0) ? Wq : (w == 1) ? Wk : (w == 2) ? Wv : Wo;
        float4 lo = *(const float4*)&W[(size_t)(2 * k2) * DM + n];
        float4 hi = *(const float4*)&W[(size_t)(2 * k2 + 1) * DM + n];
        uint32_t* dst = Wh + (size_t)w * K2 * DM + (size_t)k2 * DM + n;
        dst[0] = pk(lo.x, hi.x);
        dst[1] = pk(lo.y, hi.y);
        dst[2] = pk(lo.z, hi.z);
        dst[3] = pk(lo.w, hi.w);
    }
}

// ---------------------------------------------------------------------------
// fp16 mma GEMM: BM=128, BN=128, BK=64 (32 u32); 256 thr = 2(M) x 4(N)
// warps, per-warp 64x32; m16n8k16; 2-stage cp.async (R14-validated).
//   As stride 36 u32: a-frag bank 4g+tig+8kt  -> conflict-free
//   Bs stride 136:    b-frag bank 8(tig+nt)+g -> conflict-free
// mode 0: fp32 out | 1: Q pairs x QSCALE | 2: K interleaved | 3: V interleaved
// ---------------------------------------------------------------------------
#define AS_U (128 * 36)      // 4608
#define BS_U (32 * 136)      // 4352
#define ST_U (AS_U + BS_U)   // 8960
#define GEMM_SMEM (2 * ST_U * 4)     // 71680 B

__device__ __forceinline__ void gemm_body(
    const uint32_t* __restrict__ A, const uint32_t* __restrict__ W,
    const float* __restrict__ bias, void* __restrict__ outv, int mode)
{
    extern __shared__ uint32_t gsm[];
    const int tid  = threadIdx.x;
    const int warp = tid >> 5, lane = tid & 31;
    const int wm = warp >> 2, wn = warp & 3;
    const int g  = lane >> 2, tig = lane & 3;
    const int m0 = blockIdx.y * 128;
    const int n0 = blockIdx.x * 128;
    const uint32_t sb = smem_u32(gsm);

    float acc[4][4][4];
#pragma unroll
    for (int mt = 0; mt < 4; ++mt)
#pragma unroll
        for (int nt = 0; nt < 4; ++nt)
#pragma unroll
            for (int r = 0; r < 4; ++r) acc[mt][nt][r] = 0.f;

    auto issue_chunk = [&](int c) {
        const int k0 = c * 32;                  // u32 k-offset
        const uint32_t ab = sb + ((c & 1) * ST_U) * 4;
        const uint32_t bb = ab + AS_U * 4;
#pragma unroll
        for (int i = 0; i < 4; ++i) {
            int it = i * 256 + tid;
            int r = it >> 3, c4 = (it & 7) * 4;
            CP16(ab + (r * 36 + c4) * 4,
                 &A[(size_t)(m0 + r) * K2 + k0 + c4]);
        }
#pragma unroll
        for (int i = 0; i < 4; ++i) {
            int it = i * 256 + tid;
            int k = it >> 5, n4 = (it & 31) * 4;
            CP16(bb + (k * 136 + n4) * 4,
                 &W[(size_t)(k0 + k) * DM + n0 + n4]);
        }
    };

    issue_chunk(0);
    CP_COMMIT();

    for (int c = 0; c < 16; ++c) {
        CP_WAIT0();
        __syncthreads();
        if (c + 1 < 16) { issue_chunk(c + 1); CP_COMMIT(); }

        const uint32_t* As = gsm + (c & 1) * ST_U;
        const uint32_t* Bs = As + AS_U;
#pragma unroll
        for (int kt = 0; kt < 4; ++kt) {
            uint32_t a[4][4], b[4][2];
#pragma unroll
            for (int mt = 0; mt < 4; ++mt) {
                int row = wm * 64 + mt * 16;
                a[mt][0] = As[(row + g    ) * 36 + kt * 8 + tig];
                a[mt][1] = As[(row + g + 8) * 36 + kt * 8 + tig];
                a[mt][2] = As[(row + g    ) * 36 + kt * 8 + tig + 4];
                a[mt][3] = As[(row + g + 8) * 36 + kt * 8 + tig + 4];
            }
#pragma unroll
            for (int nt = 0; nt < 4; ++nt) {
                int coln = wn * 32 + nt * 8 + g;
                b[nt][0] = Bs[(kt * 8 + tig    ) * 136 + coln];
                b[nt][1] = Bs[(kt * 8 + tig + 4) * 136 + coln];
            }
#pragma unroll
            for (int mt = 0; mt < 4; ++mt)
#pragma unroll
                for (int nt = 0; nt < 4; ++nt)
                    mma_f16(acc[mt][nt], a[mt], b[nt][0], b[nt][1]);
        }
    }

#pragma unroll
    for (int mt = 0; mt < 4; ++mt) {
#pragma unroll
        for (int nt = 0; nt < 4; ++nt) {
            int col  = n0 + wn * 32 + nt * 8 + 2 * tig;
            float2 bv = *(const float2*)&bias[col];
#pragma unroll
            for (int hh = 0; hh < 2; ++hh) {
                int t = m0 + wm * 64 + mt * 16 + g + hh * 8;
                float ox = acc[mt][nt][hh * 2 + 0] + bv.x;
                float oy = acc[mt][nt][hh * 2 + 1] + bv.y;
                if (mode == 0) {
                    *(float2*)&((float*)outv)[(size_t)t * DM + col] =
                        make_float2(ox, oy);
                } else {
                    int bidx = t >> 11;
                    int srow = t & (SEQ - 1);
                    int head = col >> 6;
                    int dh   = col & (DH - 1);
                    int bh   = bidx * NH + head;
                    uint32_t* dst = (uint32_t*)outv;
                    if (mode == 1) {          // Q: [B,H,S,32] pairs, scaled
                        dst[((size_t)bh * SEQ + srow) * 32 + (dh >> 1)] =
                            pk(ox * QSCALE, oy * QSCALE);
                    } else if (mode == 2) {   // K: [B,H,32,SEQ] dh-interleaved
                        dst[((size_t)bh * 32 + (dh >> 1)) * SEQ + srow] =
                            pk(ox, oy);
                    } else {                  // V: [B,H,S/64,32,64] row-pairs
                        size_t u32i = (((size_t)bh * 32 + (srow >> 6)) * 32
                                       + ((srow & 63) >> 1)) * 64 + dh;
                        half* vh = (half*)outv;
                        vh[u32i * 2 + (srow & 1)]       = __float2half_rn(ox);
                        vh[(u32i + 1) * 2 + (srow & 1)] = __float2half_rn(oy);
                    }
                }
            }
        }
    }
}

__global__ __launch_bounds__(256, 2) void qkv_gemm(
    const uint32_t* __restrict__ xh, const uint32_t* __restrict__ Wh,
    const float* __restrict__ bq, const float* __restrict__ bk,
    const float* __restrict__ bv,
    uint32_t* __restrict__ Qo, uint32_t* __restrict__ Ko,
    uint32_t* __restrict__ Vo)
{
    const int z = blockIdx.z;
    const uint32_t* W = Wh + (size_t)z * K2 * DM;
    const float* bias = (z == 0) ? bq : (z == 1) ? bk : bv;
    void* out = (z == 0) ? (void*)Qo : (z == 1) ? (void*)Ko : (void*)Vo;
    gemm_body(xh, W, bias, out, z + 1);
}

__global__ __launch_bounds__(256, 2) void o_gemm(
    const uint32_t* __restrict__ ctx, const uint32_t* __restrict__ Wh,
    const float* __restrict__ bo, float* __restrict__ out)
{
    gemm_body(ctx, Wh + (size_t)3 * K2 * DM, bo, out, 0);
}

// ---------------------------------------------------------------------------
// fp16 mma flash attention. CTA 128 thr (4 warps) x 128 q-rows; warp 32 rows
// (mt=2, B-frags reused); K-blocks of 64; m16n8k16 (4 k-steps per stage).
//   Ks/Vs stride 72 u32: b-frag bank 8(tig+nt)+g -> conflict-free
//   Ps stride 36 u32: a-frag bank 4g+tig(+4)+8kt; store bank 4g+4nt+tig  -> CF
// Double-buffered cp.async K/V, one barrier per kb (R12-validated loop).
// ---------------------------------------------------------------------------
#define KS_U (32 * 72)       // 2304 u32
#define KV_U (2 * KS_U)      // 4608 per buffer (K + V)
#define PS_U (128 * 36)      // 4608
#define FLASH_SMEM ((PS_U + 2 * KV_U) * 4)   // 55296 B

__global__ __launch_bounds__(128, 2) void flash_mma(
    const uint32_t* __restrict__ Q, const uint32_t* __restrict__ K,
    const uint32_t* __restrict__ V)
{
    extern __shared__ uint32_t sm4[];
    uint32_t* Ps = sm4;
    const uint32_t sb = smem_u32(sm4);

    const int tid  = threadIdx.x;
    const int warp = tid >> 5, lane = tid & 31;
    const int g    = lane >> 2;
    const int tig  = lane & 3;
    const int qt = blockIdx.x;
    const int h  = blockIdx.y;
    const int b  = blockIdx.z;
    const int bh = b * NH + h;

    const uint32_t* Qg = Q + ((size_t)bh * SEQ + (size_t)qt * 128) * 32;
    const uint32_t* Kg = K + (size_t)bh * 32 * SEQ;
    const uint32_t* Vg = V + (size_t)bh * 32 * SEQ;   // blocks of 2048 u32

    auto issue_kv = [&](int kb) {
        const uint32_t kbase = sb + (PS_U + (kb & 1) * KV_U) * 4;
        const uint32_t vbase = kbase + KS_U * 4;
        const uint32_t* vblk = Vg + (size_t)kb * 2048;
#pragma unroll
        for (int i = 0; i < 4; ++i) {
            int it = i * 128 + tid;
            int r = it >> 4, c4 = (it & 15) * 4;
            CP16(kbase + (r * 72 + c4) * 4,
                 &Kg[(size_t)r * SEQ + kb * 64 + c4]);
            CP16(vbase + (r * 72 + c4) * 4, &vblk[r * 64 + c4]);
        }
    };

    issue_kv(0);
    CP_COMMIT();

    // Q fragments straight from gmem (natural pair layout)
    uint32_t qf[2][4][4];
#pragma unroll
    for (int mt = 0; mt < 2; ++mt) {
        const int row = warp * 32 + mt * 16 + g;
#pragma unroll
        for (int kt = 0; kt < 4; ++kt) {
            qf[mt][kt][0] = Qg[(size_t)row * 32 + kt * 8 + tig];
            qf[mt][kt][1] = Qg[(size_t)(row + 8) * 32 + kt * 8 + tig];
            qf[mt][kt][2] = Qg[(size_t)row * 32 + kt * 8 + tig + 4];
            qf[mt][kt][3] = Qg[(size_t)(row + 8) * 32 + kt * 8 + tig + 4];
        }
    }

    float o[2][8][4];
#pragma unroll
    for (int mt = 0; mt < 2; ++mt)
#pragma unroll
        for (int nt = 0; nt < 8; ++nt)
#pragma unroll
            for (int r = 0; r < 4; ++r) o[mt][nt][r] = 0.f;
    float m[2][2], l[2][2];
#pragma unroll
    for (int mt = 0; mt < 2; ++mt) {
        m[mt][0] = m[mt][1] = -1e30f;
        l[mt][0] = l[mt][1] = 0.f;
    }

    for (int kb = 0; kb < SEQ / 64; ++kb) {
        CP_WAIT0();
        __syncthreads();
        if (kb + 1 < SEQ / 64) { issue_kv(kb + 1); CP_COMMIT(); }

        const uint32_t* Ks = sm4 + PS_U + (kb & 1) * KV_U;
        const uint32_t* Vs = Ks + KS_U;

        // S = Q @ K^T : 32 rows x 64 cols per warp, B-frags shared across mt
        float s[2][8][4];
#pragma unroll
        for (int mt = 0; mt < 2; ++mt)
#pragma unroll
            for (int nt = 0; nt < 8; ++nt)
#pragma unroll
                for (int r = 0; r < 4; ++r) s[mt][nt][r] = 0.f;
#pragma unroll
        for (int kt = 0; kt < 4; ++kt) {
#pragma unroll
            for (int nt = 0; nt < 8; ++nt) {
                uint32_t b0 = Ks[(kt * 8 + tig    ) * 72 + nt * 8 + g];
                uint32_t b1 = Ks[(kt * 8 + tig + 4) * 72 + nt * 8 + g];
                mma_f16(s[0][nt], qf[0][kt], b0, b1);
                mma_f16(s[1][nt], qf[1][kt], b0, b1);
            }
        }

        // Online softmax in log2 domain (scores pre-scaled by log2e)
#pragma unroll
        for (int mt = 0; mt < 2; ++mt) {
            float mx0 = -1e30f, mx1 = -1e30f;
#pragma unroll
            for (int nt = 0; nt < 8; ++nt) {
                mx0 = fmaxf(mx0, fmaxf(s[mt][nt][0], s[mt][nt][1]));
                mx1 = fmaxf(mx1, fmaxf(s[mt][nt][2], s[mt][nt][3]));
            }
#pragma unroll
            for (int off = 1; off < 4; off <<= 1) {
                mx0 = fmaxf(mx0, __shfl_xor_sync(0xffffffffu, mx0, off, 4));
                mx1 = fmaxf(mx1, __shfl_xor_sync(0xffffffffu, mx1, off, 4));
            }
            float mn0 = fmaxf(m[mt][0], mx0), mn1 = fmaxf(m[mt][1], mx1);
            float c0 = ex2(m[mt][0] - mn0), c1 = ex2(m[mt][1] - mn1);
            m[mt][0] = mn0; m[mt][1] = mn1;

            float sum0 = 0.f, sum1 = 0.f;
            const int row = warp * 32 + mt * 16 + g;
#pragma unroll
            for (int nt = 0; nt < 8; ++nt) {
                s[mt][nt][0] = ex2(s[mt][nt][0] - mn0);
                s[mt][nt][1] = ex2(s[mt][nt][1] - mn0);
                s[mt][nt][2] = ex2(s[mt][nt][2] - mn1);
                s[mt][nt][3] = ex2(s[mt][nt][3] - mn1);
                sum0 += s[mt][nt][0] + s[mt][nt][1];
                sum1 += s[mt][nt][2] + s[mt][nt][3];
                Ps[row * 36 + nt * 4 + tig] = pk(s[mt][nt][0], s[mt][nt][1]);
                Ps[(row + 8) * 36 + nt * 4 + tig] =
                    pk(s[mt][nt][2], s[mt][nt][3]);
            }
#pragma unroll
            for (int off = 1; off < 4; off <<= 1) {
                sum0 += __shfl_xor_sync(0xffffffffu, sum0, off, 4);
                sum1 += __shfl_xor_sync(0xffffffffu, sum1, off, 4);
            }
            l[mt][0] = l[mt][0] * c0 + sum0;
            l[mt][1] = l[mt][1] * c1 + sum1;
#pragma unroll
            for (int nt = 0; nt < 8; ++nt) {
                o[mt][nt][0] *= c0; o[mt][nt][1] *= c0;
                o[mt][nt][2] *= c1; o[mt][nt][3] *= c1;
            }
        }
        __syncwarp();   // P rows are warp-private

        // O += P @ V  (V B-frags shared across mt)
#pragma unroll
        for (int kt = 0; kt < 4; ++kt) {
            uint32_t a0[4], a1[4];
            const int r0 = warp * 32 + g;
            a0[0] = Ps[r0 * 36 + kt * 8 + tig];
            a0[1] = Ps[(r0 + 8) * 36 + kt * 8 + tig];
            a0[2] = Ps[r0 * 36 + kt * 8 + tig + 4];
            a0[3] = Ps[(r0 + 8) * 36 + kt * 8 + tig + 4];
            a1[0] = Ps[(r0 + 16) * 36 + kt * 8 + tig];
            a1[1] = Ps[(r0 + 24) * 36 + kt * 8 + tig];
            a1[2] = Ps[(r0 + 16) * 36 + kt * 8 + tig + 4];
            a1[3] = Ps[(r0 + 24) * 36 + kt * 8 + tig + 4];
#pragma unroll
            for (int nt = 0; nt < 8; ++nt) {
                uint32_t b0 = Vs[(kt * 8 + tig    ) * 72 + nt * 8 + g];
                uint32_t b1 = Vs[(kt * 8 + tig + 4) * 72 + nt * 8 + g];
                mma_f16(o[0][nt], a0, b0, b1);
                mma_f16(o[1][nt], a1, b0, b1);
            }
        }
    }

    // Epilogue: normalize, write ctx as fp16 pairs
#pragma unroll
    for (int mt = 0; mt < 2; ++mt) {
        const float inv0 = 1.f / l[mt][0], inv1 = 1.f / l[mt][1];
        const int row0 = qt * 128 + warp * 32 + mt * 16 + g;
#pragma unroll
        for (int nt = 0; nt < 8; ++nt) {
            int col2 = h * 32 + nt * 4 + tig;   // u32 column in ctx
            g_ctxh[(size_t)(b * SEQ + row0) * K2 + col2] =
                pk(o[mt][nt][0] * inv0, o[mt][nt][1] * inv0);
            g_ctxh[(size_t)(b * SEQ + row0 + 8) * K2 + col2] =
                pk(o[mt][nt][2] * inv1, o[mt][nt][3] * inv1);
        }
    }
}

// ---------------------------------------------------------------------------
// Launch
// ---------------------------------------------------------------------------
extern "C" void kernel_launch(void* const* d_in, const int* in_sizes, int n_in,
                              void* d_out, int out_size)
{
    const float* x  = (const float*)d_in[0];
    const float* Wq = (const float*)d_in[1];
    const float* bq = (const float*)d_in[2];
    const float* Wk = (const float*)d_in[3];
    const float* bk = (const float*)d_in[4];
    const float* Wv = (const float*)d_in[5];
    const float* bv = (const float*)d_in[6];
    const float* Wo = (const float*)d_in[7];
    const float* bo = (const float*)d_in[8];
    float* out = (float*)d_out;

    uint32_t *Qp, *Kp, *Vp, *Cp, *Xp, *Wp;
    cudaGetSymbolAddress((void**)&Qp, g_Qh);
    cudaGetSymbolAddress((void**)&Kp, g_Kh);
    cudaGetSymbolAddress((void**)&Vp, g_Vh);
    cudaGetSymbolAddress((void**)&Cp, g_ctxh);
    cudaGetSymbolAddress((void**)&Xp, g_xh);
    cudaGetSymbolAddress((void**)&Wp, g_Wh);

    cudaFuncSetAttribute(flash_mma,
                         cudaFuncAttributeMaxDynamicSharedMemorySize, FLASH_SMEM);
    cudaFuncSetAttribute(qkv_gemm,
                         cudaFuncAttributeMaxDynamicSharedMemorySize, GEMM_SMEM);
    cudaFuncSetAttribute(o_gemm,
                         cudaFuncAttributeMaxDynamicSharedMemorySize, GEMM_SMEM);

    // Prep: x natural pairs + 4 weights interleaved, one launch
    prep_all<<<(int)((XTHR + 4 * WTHR) / 256), 256>>>(
        x, Wq, Wk, Wv, Wo, Xp, Wp);

    qkv_gemm<<<dim3(DM / 128, NTOK / 128, 3), 256, GEMM_SMEM>>>(
        Xp, Wp, bq, bk, bv, Qp, Kp, Vp);

    flash_mma<<<dim3(SEQ / 128, NH, B_SZ), 128, FLASH_SMEM>>>(Qp, Kp, Vp);

    o_gemm<<<dim3(DM / 128, NTOK / 128), 256, GEMM_SMEM>>>(Cp, Wp, bo, out);
}

// round 17
// speedup vs baseline: 1.9094x; 1.6041x over previous
#include <cuda_runtime.h>
#include <cuda_fp16.h>
#include <math.h>
#include <stdint.h>

// Problem constants
#define B_SZ 4
#define SEQ  2048
#define DM   1024
#define NH   16
#define DH   64
#define NTOK (B_SZ * SEQ)   // 8192
#define K2   (DM / 2)       // 512 u32 per row of x/ctx

// ---------------------------------------------------------------------------
// Scratch (device globals) — packed fp16 pairs (u32).
// g_xh:  [NTOK][512]        natural pairs of x
// g_Wh:  4 x [1024 n][512]  n-major, k2 p8-permuted: u32[n][p8(k2)] = (W[2k2][n], W[2k2+1][n])
// g_Qh:  [B,H,S,32]  p8 in k2 (Q * QSCALE)
// g_Kh:  [B,H,S,32]  p8 in k2
// g_Vh:  [B,H,S/64,64 dh,32] p8 in j2 (key-pair within 64-block)
// g_ctxh:[NTOK][512] natural pairs
// p8(k) = (k&~7) + 2*(k&3) + ((k>>2)&1): pairs (t, t+4) adjacent
// ---------------------------------------------------------------------------
__device__ uint32_t g_xh[(size_t)NTOK * K2];
__device__ uint32_t g_Wh[(size_t)4 * DM * K2];
__device__ uint32_t g_Qh[(size_t)B_SZ * NH * SEQ * 32];
__device__ uint32_t g_Kh[(size_t)B_SZ * NH * SEQ * 32];
__device__ uint32_t g_Vh[(size_t)B_SZ * NH * SEQ * 32];
__device__ uint32_t g_ctxh[(size_t)NTOK * K2];

#define QSCALE 0.180336880f   // 0.125 * log2(e)

__device__ __forceinline__ int p8(int k) {
    return (k & ~7) + ((k & 3) << 1) + ((k >> 2) & 1);
}
__device__ __forceinline__ uint32_t pk(float a, float b) {
    half2 h = __floats2half2_rn(a, b);
    return *(uint32_t*)&h;
}
__device__ __forceinline__ float ex2(float x) {
    float y;
    asm("ex2.approx.f32 %0, %1;" : "=f"(y) : "f"(x));
    return y;
}
__device__ __forceinline__ uint32_t smem_u32(const void* p) {
    uint32_t a;
    asm("{ .reg .u64 t; cvta.to.shared.u64 t, %1; cvt.u32.u64 %0, t; }"
        : "=r"(a) : "l"(p));
    return a;
}
__device__ __forceinline__ void mma_f16(float* c, const uint32_t* a,
                                        uint32_t b0, uint32_t b1) {
    asm volatile(
        "mma.sync.aligned.m16n8k16.row.col.f32.f16.f16.f32 "
        "{%0,%1,%2,%3}, {%4,%5,%6,%7}, {%8,%9}, {%0,%1,%2,%3};"
        : "+f"(c[0]), "+f"(c[1]), "+f"(c[2]), "+f"(c[3])
        : "r"(a[0]), "r"(a[1]), "r"(a[2]), "r"(a[3]), "r"(b0), "r"(b1));
}
__device__ __forceinline__ void ldm_x4(uint32_t* r, uint32_t addr) {
    asm volatile(
        "ldmatrix.sync.aligned.m8n8.x4.shared.b16 {%0,%1,%2,%3}, [%4];"
        : "=r"(r[0]), "=r"(r[1]), "=r"(r[2]), "=r"(r[3]) : "r"(addr));
}

#define CP16(dst32, src) \
    asm volatile("cp.async.cg.shared.global [%0], [%1], 16;" \
                 :: "r"(dst32), "l"(src) : "memory")
#define CP_COMMIT() asm volatile("cp.async.commit_group;" ::: "memory")
#define CP_WAIT0()  asm volatile("cp.async.wait_group 0;" ::: "memory")

// ---------------------------------------------------------------------------
// Prep (single launch): x -> natural pairs; W -> n-major p8-interleaved.
// ---------------------------------------------------------------------------
#define NX   ((size_t)NTOK * DM)     // floats in x
#define NW   ((size_t)DM * DM)       // floats per W
#define XTHR (NX / 4)
#define WTHR (NW / 8)

__global__ __launch_bounds__(256) void prep_all(
    const float* __restrict__ x,
    const float* __restrict__ Wq, const float* __restrict__ Wk,
    const float* __restrict__ Wv, const float* __restrict__ Wo,
    uint32_t* __restrict__ xh, uint32_t* __restrict__ Wh)
{
    size_t i = (size_t)blockIdx.x * 256 + threadIdx.x;
    if (i < XTHR) {
        float4 v = *(const float4*)&x[i * 4];
        xh[i * 2 + 0] = pk(v.x, v.y);
        xh[i * 2 + 1] = pk(v.z, v.w);
    } else {
        size_t j = i - XTHR;
        int w = (int)(j / WTHR);
        size_t r = j % WTHR;
        int k2 = (int)(r >> 8);          // 0..511
        int n  = (int)(r & 255) * 4;     // 0..1020
        const float* W = (w == 0) ? Wq : (w == 1) ? Wk : (w == 2) ? Wv : Wo;
        float4 lo = *(const float4*)&W[(size_t)(2 * k2) * DM + n];
        float4 hi = *(const float4*)&W[(size_t)(2 * k2 + 1) * DM + n];
        uint32_t* dst = Wh + (size_t)w * DM * K2 + p8(k2);
        dst[(size_t)(n + 0) * K2] = pk(lo.x, hi.x);
        dst[(size_t)(n + 1) * K2] = pk(lo.y, hi.y);
        dst[(size_t)(n + 2) * K2] = pk(lo.z, hi.z);
        dst[(size_t)(n + 3) * K2] = pk(lo.w, hi.w);
    }
}

// ---------------------------------------------------------------------------
// fp16 mma GEMM: BM=128, BN=128, BK=64; 256 thr = 2(M)x4(N) warps,
// per-warp 64x32; 2-stage cp.async (R14/R16-validated loop).
//   As [128][36] u32 natural k2 rows -> a-frags via ldmatrix.x4 (banks 4row, CF)
//   Bs [128 n][40] u32 p8 k2 cols   -> b-frags via LDS.64 (banks 8g+2tig, CF/phase)
// mode 0: fp32 out | 1: Q (p8, xQSCALE) | 2: K (p8) | 3: V (p8 j2, transposed)
// ---------------------------------------------------------------------------
#define AS_U (128 * 36)      // 4608
#define BS_U (128 * 40)      // 5120
#define ST_U (AS_U + BS_U)   // 9728
#define GEMM_SMEM (2 * ST_U * 4)     // 77824 B

__device__ __forceinline__ void gemm_body(
    const uint32_t* __restrict__ A, const uint32_t* __restrict__ W,
    const float* __restrict__ bias, void* __restrict__ outv, int mode)
{
    extern __shared__ uint32_t gsm[];
    const int tid  = threadIdx.x;
    const int warp = tid >> 5, lane = tid & 31;
    const int wm = warp >> 2, wn = warp & 3;
    const int g  = lane >> 2, tig = lane & 3;
    const int lrow = lane & 15, lseg = lane >> 4;   // ldmatrix lane mapping
    const int m0 = blockIdx.y * 128;
    const int n0 = blockIdx.x * 128;
    const uint32_t sb = smem_u32(gsm);

    float acc[4][4][4];
#pragma unroll
    for (int mt = 0; mt < 4; ++mt)
#pragma unroll
        for (int nt = 0; nt < 4; ++nt)
#pragma unroll
            for (int r = 0; r < 4; ++r) acc[mt][nt][r] = 0.f;

    auto issue_chunk = [&](int c) {
        const int k0 = c * 32;                  // u32 k-offset
        const uint32_t ab = sb + ((c & 1) * ST_U) * 4;
        const uint32_t bb = ab + AS_U * 4;
#pragma unroll
        for (int i = 0; i < 4; ++i) {
            int it = i * 256 + tid;
            int r = it >> 3, c4 = (it & 7) * 4;
            CP16(ab + (r * 36 + c4) * 4,
                 &A[(size_t)(m0 + r) * K2 + k0 + c4]);
        }
#pragma unroll
        for (int i = 0; i < 4; ++i) {
            int it = i * 256 + tid;
            int r = it >> 3, c4 = (it & 7) * 4;
            CP16(bb + (r * 40 + c4) * 4,
                 &W[(size_t)(n0 + r) * K2 + k0 + c4]);
        }
    };

    issue_chunk(0);
    CP_COMMIT();

    for (int c = 0; c < 16; ++c) {
        CP_WAIT0();
        __syncthreads();
        if (c + 1 < 16) { issue_chunk(c + 1); CP_COMMIT(); }

        const uint32_t abase = sb + ((c & 1) * ST_U) * 4;
        const uint32_t* Bs = gsm + (c & 1) * ST_U + AS_U;
#pragma unroll
        for (int kt = 0; kt < 4; ++kt) {
            uint32_t a[4][4], b[4][2];
#pragma unroll
            for (int mt = 0; mt < 4; ++mt)
                ldm_x4(a[mt], abase +
                       ((wm * 64 + mt * 16 + lrow) * 36 + kt * 8 + lseg * 4) * 4);
#pragma unroll
            for (int nt = 0; nt < 4; ++nt) {
                uint2 bb = *(const uint2*)
                    &Bs[(wn * 32 + nt * 8 + g) * 40 + kt * 8 + 2 * tig];
                b[nt][0] = bb.x; b[nt][1] = bb.y;
            }
#pragma unroll
            for (int mt = 0; mt < 4; ++mt)
#pragma unroll
                for (int nt = 0; nt < 4; ++nt)
                    mma_f16(acc[mt][nt], a[mt], b[nt][0], b[nt][1]);
        }
    }

#pragma unroll
    for (int mt = 0; mt < 4; ++mt) {
#pragma unroll
        for (int nt = 0; nt < 4; ++nt) {
            int col  = n0 + wn * 32 + nt * 8 + 2 * tig;
            float2 bv = *(const float2*)&bias[col];
#pragma unroll
            for (int hh = 0; hh < 2; ++hh) {
                int t = m0 + wm * 64 + mt * 16 + g + hh * 8;
                float ox = acc[mt][nt][hh * 2 + 0] + bv.x;
                float oy = acc[mt][nt][hh * 2 + 1] + bv.y;
                if (mode == 0) {
                    *(float2*)&((float*)outv)[(size_t)t * DM + col] =
                        make_float2(ox, oy);
                } else {
                    int bidx = t >> 11;
                    int srow = t & (SEQ - 1);
                    int head = col >> 6;
                    int dh   = col & (DH - 1);
                    int bh   = bidx * NH + head;
                    uint32_t* dst = (uint32_t*)outv;
                    if (mode == 1) {
                        dst[((size_t)bh * SEQ + srow) * 32 + p8(dh >> 1)] =
                            pk(ox * QSCALE, oy * QSCALE);
                    } else if (mode == 2) {
                        dst[((size_t)bh * SEQ + srow) * 32 + p8(dh >> 1)] =
                            pk(ox, oy);
                    } else {    // V: [bh][blk][dh][p8(j2)] halves
                        size_t base = (((size_t)bh * 32 + (srow >> 6)) * 64
                                       + dh) * 32 + p8((srow & 63) >> 1);
                        half* vh = (half*)outv;
                        vh[base * 2 + (srow & 1)]        = __float2half_rn(ox);
                        vh[(base + 32) * 2 + (srow & 1)] = __float2half_rn(oy);
                    }
                }
            }
        }
    }
}

__global__ __launch_bounds__(256, 2) void qkv_gemm(
    const uint32_t* __restrict__ xh, const uint32_t* __restrict__ Wh,
    const float* __restrict__ bq, const float* __restrict__ bk,
    const float* __restrict__ bv,
    uint32_t* __restrict__ Qo, uint32_t* __restrict__ Ko,
    uint32_t* __restrict__ Vo)
{
    const int z = blockIdx.z;
    const uint32_t* W = Wh + (size_t)z * DM * K2;
    const float* bias = (z == 0) ? bq : (z == 1) ? bk : bv;
    void* out = (z == 0) ? (void*)Qo : (z == 1) ? (void*)Ko : (void*)Vo;
    gemm_body(xh, W, bias, out, z + 1);
}

__global__ __launch_bounds__(256, 2) void o_gemm(
    const uint32_t* __restrict__ ctx, const uint32_t* __restrict__ Wh,
    const float* __restrict__ bo, float* __restrict__ out)
{
    gemm_body(ctx, Wh + (size_t)3 * DM * K2, bo, out, 0);
}

// ---------------------------------------------------------------------------
// fp16 mma flash attention. CTA 128 thr (4 warps) x 128 q-rows; warp 32 rows
// (mt=2, B-frags reused); K-blocks of 64; m16n8k16.
//   Ks [64 s][40]  p8 k2  -> QK b-frags via LDS.64 (CF/phase)
//   Vs [64 dh][40] p8 j2  -> PV b-frags via LDS.64 (CF/phase)
//   Ps [128][36] natural  -> PV a-frags via ldmatrix.x4 (banks 4row, CF)
// Double-buffered cp.async K/V, one barrier per kb.
// ---------------------------------------------------------------------------
#define KS_U (64 * 40)       // 2560 u32 (K tile)
#define KV_U (2 * KS_U)      // 5120 per buffer (K + V)
#define PS_U (128 * 36)      // 4608
#define FLASH_SMEM ((PS_U + 2 * KV_U) * 4)   // 59392 B

__global__ __launch_bounds__(128, 2) void flash_mma(
    const uint32_t* __restrict__ Q, const uint32_t* __restrict__ K,
    const uint32_t* __restrict__ V)
{
    extern __shared__ uint32_t sm4[];
    uint32_t* Ps = sm4;
    const uint32_t sb = smem_u32(sm4);

    const int tid  = threadIdx.x;
    const int warp = tid >> 5, lane = tid & 31;
    const int g    = lane >> 2;
    const int tig  = lane & 3;
    const int lrow = lane & 15, lseg = lane >> 4;
    const int qt = blockIdx.x;
    const int h  = blockIdx.y;
    const int b  = blockIdx.z;
    const int bh = b * NH + h;

    const uint32_t* Qg = Q + ((size_t)bh * SEQ + (size_t)qt * 128) * 32;
    const uint32_t* Kg = K + (size_t)bh * SEQ * 32;
    const uint32_t* Vg = V + (size_t)bh * 32 * 2048;

    auto issue_kv = [&](int kb) {
        const uint32_t kbase = sb + (PS_U + (kb & 1) * KV_U) * 4;
        const uint32_t vbase = kbase + KS_U * 4;
#pragma unroll
        for (int i = 0; i < 4; ++i) {
            int it = i * 128 + tid;
            int r = it >> 3, c4 = (it & 7) * 4;
            CP16(kbase + (r * 40 + c4) * 4,
                 &Kg[(size_t)(kb * 64 + r) * 32 + c4]);
            CP16(vbase + (r * 40 + c4) * 4,
                 &Vg[(size_t)kb * 2048 + r * 32 + c4]);
        }
    };

    issue_kv(0);
    CP_COMMIT();

    // Q fragments from gmem (p8 pairs -> LDG.64)
    uint32_t qf[2][4][4];
#pragma unroll
    for (int mt = 0; mt < 2; ++mt) {
        const int row = warp * 32 + mt * 16 + g;
#pragma unroll
        for (int kt = 0; kt < 4; ++kt) {
            uint2 ua = *(const uint2*)&Qg[(size_t)row * 32 + kt * 8 + 2 * tig];
            uint2 ub = *(const uint2*)&Qg[(size_t)(row + 8) * 32 + kt * 8 + 2 * tig];
            qf[mt][kt][0] = ua.x; qf[mt][kt][2] = ua.y;
            qf[mt][kt][1] = ub.x; qf[mt][kt][3] = ub.y;
        }
    }

    float o[2][8][4];
#pragma unroll
    for (int mt = 0; mt < 2; ++mt)
#pragma unroll
        for (int nt = 0; nt < 8; ++nt)
#pragma unroll
            for (int r = 0; r < 4; ++r) o[mt][nt][r] = 0.f;
    float m[2][2], l[2][2];
#pragma unroll
    for (int mt = 0; mt < 2; ++mt) {
        m[mt][0] = m[mt][1] = -1e30f;
        l[mt][0] = l[mt][1] = 0.f;
    }

    for (int kb = 0; kb < SEQ / 64; ++kb) {
        CP_WAIT0();
        __syncthreads();
        if (kb + 1 < SEQ / 64) { issue_kv(kb + 1); CP_COMMIT(); }

        const uint32_t* Ks = sm4 + PS_U + (kb & 1) * KV_U;
        const uint32_t* Vs = Ks + KS_U;

        // S = Q @ K^T : 32 rows x 64 cols per warp
        float s[2][8][4];
#pragma unroll
        for (int mt = 0; mt < 2; ++mt)
#pragma unroll
            for (int nt = 0; nt < 8; ++nt)
#pragma unroll
                for (int r = 0; r < 4; ++r) s[mt][nt][r] = 0.f;
#pragma unroll
        for (int kt = 0; kt < 4; ++kt) {
#pragma unroll
            for (int nt = 0; nt < 8; ++nt) {
                uint2 bb = *(const uint2*)
                    &Ks[(nt * 8 + g) * 40 + kt * 8 + 2 * tig];
                mma_f16(s[0][nt], qf[0][kt], bb.x, bb.y);
                mma_f16(s[1][nt], qf[1][kt], bb.x, bb.y);
            }
        }

        // Online softmax in log2 domain
#pragma unroll
        for (int mt = 0; mt < 2; ++mt) {
            float mx0 = -1e30f, mx1 = -1e30f;
#pragma unroll
            for (int nt = 0; nt < 8; ++nt) {
                mx0 = fmaxf(mx0, fmaxf(s[mt][nt][0], s[mt][nt][1]));
                mx1 = fmaxf(mx1, fmaxf(s[mt][nt][2], s[mt][nt][3]));
            }
#pragma unroll
            for (int off = 1; off < 4; off <<= 1) {
                mx0 = fmaxf(mx0, __shfl_xor_sync(0xffffffffu, mx0, off, 4));
                mx1 = fmaxf(mx1, __shfl_xor_sync(0xffffffffu, mx1, off, 4));
            }
            float mn0 = fmaxf(m[mt][0], mx0), mn1 = fmaxf(m[mt][1], mx1);
            float c0 = ex2(m[mt][0] - mn0), c1 = ex2(m[mt][1] - mn1);
            m[mt][0] = mn0; m[mt][1] = mn1;

            float sum0 = 0.f, sum1 = 0.f;
            const int row = warp * 32 + mt * 16 + g;
#pragma unroll
            for (int nt = 0; nt < 8; ++nt) {
                s[mt][nt][0] = ex2(s[mt][nt][0] - mn0);
                s[mt][nt][1] = ex2(s[mt][nt][1] - mn0);
                s[mt][nt][2] = ex2(s[mt][nt][2] - mn1);
                s[mt][nt][3] = ex2(s[mt][nt][3] - mn1);
                sum0 += s[mt][nt][0] + s[mt][nt][1];
                sum1 += s[mt][nt][2] + s[mt][nt][3];
                Ps[row * 36 + nt * 4 + tig] = pk(s[mt][nt][0], s[mt][nt][1]);
                Ps[(row + 8) * 36 + nt * 4 + tig] =
                    pk(s[mt][nt][2], s[mt][nt][3]);
            }
#pragma unroll
            for (int off = 1; off < 4; off <<= 1) {
                sum0 += __shfl_xor_sync(0xffffffffu, sum0, off, 4);
                sum1 += __shfl_xor_sync(0xffffffffu, sum1, off, 4);
            }
            l[mt][0] = l[mt][0] * c0 + sum0;
            l[mt][1] = l[mt][1] * c1 + sum1;
#pragma unroll
            for (int nt = 0; nt < 8; ++nt) {
                o[mt][nt][0] *= c0; o[mt][nt][1] *= c0;
                o[mt][nt][2] *= c1; o[mt][nt][3] *= c1;
            }
        }
        __syncwarp();   // P rows are warp-private

        // O += P @ V
#pragma unroll
        for (int kt = 0; kt < 4; ++kt) {
            uint32_t a0[4], a1[4];
            ldm_x4(a0, sb + ((warp * 32 + lrow) * 36 + kt * 8 + lseg * 4) * 4);
            ldm_x4(a1, sb + ((warp * 32 + 16 + lrow) * 36 + kt * 8 + lseg * 4) * 4);
#pragma unroll
            for (int nt = 0; nt < 8; ++nt) {
                uint2 bb = *(const uint2*)
                    &Vs[(nt * 8 + g) * 40 + kt * 8 + 2 * tig];
                mma_f16(o[0][nt], a0, bb.x, bb.y);
                mma_f16(o[1][nt], a1, bb.x, bb.y);
            }
        }
    }

    // Epilogue: normalize, write ctx as natural fp16 pairs
#pragma unroll
    for (int mt = 0; mt < 2; ++mt) {
        const float inv0 = 1.f / l[mt][0], inv1 = 1.f / l[mt][1];
        const int row0 = qt * 128 + warp * 32 + mt * 16 + g;
#pragma unroll
        for (int nt = 0; nt < 8; ++nt) {
            int col2 = h * 32 + nt * 4 + tig;
            g_ctxh[(size_t)(b * SEQ + row0) * K2 + col2] =
                pk(o[mt][nt][0] * inv0, o[mt][nt][1] * inv0);
            g_ctxh[(size_t)(b * SEQ + row0 + 8) * K2 + col2] =
                pk(o[mt][nt][2] * inv1, o[mt][nt][3] * inv1);
        }
    }
}

// ---------------------------------------------------------------------------
// Launch
// ---------------------------------------------------------------------------
extern "C" void kernel_launch(void* const* d_in, const int* in_sizes, int n_in,
                              void* d_out, int out_size)
{
    const float* x  = (const float*)d_in[0];
    const float* Wq = (const float*)d_in[1];
    const float* bq = (const float*)d_in[2];
    const float* Wk = (const float*)d_in[3];
    const float* bk = (const float*)d_in[4];
    const float* Wv = (const float*)d_in[5];
    const float* bv = (const float*)d_in[6];
    const float* Wo = (const float*)d_in[7];
    const float* bo = (const float*)d_in[8];
    float* out = (float*)d_out;

    uint32_t *Qp, *Kp, *Vp, *Cp, *Xp, *Wp;
    cudaGetSymbolAddress((void**)&Qp, g_Qh);
    cudaGetSymbolAddress((void**)&Kp, g_Kh);
    cudaGetSymbolAddress((void**)&Vp, g_Vh);
    cudaGetSymbolAddress((void**)&Cp, g_ctxh);
    cudaGetSymbolAddress((void**)&Xp, g_xh);
    cudaGetSymbolAddress((void**)&Wp, g_Wh);

    cudaFuncSetAttribute(flash_mma,
                         cudaFuncAttributeMaxDynamicSharedMemorySize, FLASH_SMEM);
    cudaFuncSetAttribute(qkv_gemm,
                         cudaFuncAttributeMaxDynamicSharedMemorySize, GEMM_SMEM);
    cudaFuncSetAttribute(o_gemm,
                         cudaFuncAttributeMaxDynamicSharedMemorySize, GEMM_SMEM);

    prep_all<<<(int)((XTHR + 4 * WTHR) / 256), 256>>>(
        x, Wq, Wk, Wv, Wo, Xp, Wp);

    qkv_gemm<<<dim3(DM / 128, NTOK / 128, 3), 256, GEMM_SMEM>>>(
        Xp, Wp, bq, bk, bv, Qp, Kp, Vp);

    flash_mma<<<dim3(SEQ / 128, NH, B_SZ), 128, FLASH_SMEM>>>(Qp, Kp, Vp);

    o_gemm<<<dim3(DM / 128, NTOK / 128), 256, GEMM_SMEM>>>(Cp, Wp, bo, out);
}